// round 2
// baseline (speedup 1.0000x reference)
#include <cuda_runtime.h>
#include <cuda_bf16.h>
#include <math.h>

// ---------------------------------------------------------------------------
// Problem constants
// ---------------------------------------------------------------------------
#define NB   2            // batch
#define S    2048         // seq len
#define DM   1024         // d_model
#define NH   16           // heads
#define HD   64           // head dim
#define DFF  4096         // ffn dim
#define TOK  (NB * S)     // 4096 tokens
#define LN_EPS 1e-5f

// ---------------------------------------------------------------------------
// Scratch (static device globals; no runtime allocation allowed)
// ---------------------------------------------------------------------------
__device__ float g_xn [(size_t)TOK * DM];   // layernorm output (reused for both LNs)
__device__ float g_q  [(size_t)TOK * DM];
__device__ float g_k  [(size_t)TOK * DM];
__device__ float g_v  [(size_t)TOK * DM];
__device__ float g_ao [(size_t)TOK * DM];   // attention output (pre-proj)
__device__ float g_x2 [(size_t)TOK * DM];   // residual after attention
__device__ float g_ff [(size_t)TOK * DFF];  // ffn hidden

// ---------------------------------------------------------------------------
// LayerNorm: one block per row (1024 floats), 256 threads, float4
// ---------------------------------------------------------------------------
__global__ __launch_bounds__(256) void ln_kernel(
    const float* __restrict__ x, const float* __restrict__ g,
    const float* __restrict__ b, float* __restrict__ y)
{
    int row = blockIdx.x;
    int t = threadIdx.x;
    const float4* xr = (const float4*)(x + (size_t)row * DM);
    float4 v = xr[t];
    float sum = v.x + v.y + v.z + v.w;
    float sq  = v.x*v.x + v.y*v.y + v.z*v.z + v.w*v.w;

    __shared__ float s1[256], s2[256];
    s1[t] = sum; s2[t] = sq;
    __syncthreads();
    #pragma unroll
    for (int st = 128; st > 0; st >>= 1) {
        if (t < st) { s1[t] += s1[t + st]; s2[t] += s2[t + st]; }
        __syncthreads();
    }
    float mu  = s1[0] * (1.0f / DM);
    float var = s2[0] * (1.0f / DM) - mu * mu;
    float inv = rsqrtf(var + LN_EPS);

    float4 gv = ((const float4*)g)[t];
    float4 bv = ((const float4*)b)[t];
    float4 o;
    o.x = (v.x - mu) * inv * gv.x + bv.x;
    o.y = (v.y - mu) * inv * gv.y + bv.y;
    o.z = (v.z - mu) * inv * gv.z + bv.z;
    o.w = (v.w - mu) * inv * gv.w + bv.w;
    ((float4*)(y + (size_t)row * DM))[t] = o;
}

// ---------------------------------------------------------------------------
// SGEMM: C[M,N] = A[M,K] @ B[K,N]  (+bias) (+residual) (relu)
// 128x128 block tile, BK=8, 8x8 per thread, 256 threads.
// Double-buffered smem + register-staged prefetch (1 syncthreads / K-tile).
// Requires M%128==0, N%128==0, K%8==0 (true for all shapes here).
// ---------------------------------------------------------------------------
template<bool BIAS, bool RELU, bool RES>
__global__ __launch_bounds__(256) void sgemm128(
    int M, int N, int K,
    const float* __restrict__ A, const float* __restrict__ B,
    const float* __restrict__ bias, const float* __restrict__ res,
    float* __restrict__ C)
{
    constexpr int BM = 128, BN = 128, BK = 8, TM = 8, TN = 8;
    __shared__ float As[2][BK][BM];
    __shared__ float Bs[2][BK][BN];

    int tid = threadIdx.x;
    int tr = tid >> 4;          // 0..15
    int tc = tid & 15;          // 0..15
    int arow = tid >> 1;        // 0..127
    int acol = (tid & 1) * 4;   // 0 or 4
    int brow = tid >> 5;        // 0..7
    int bcol = (tid & 31) * 4;  // 0..124

    const float* Ablk = A + (size_t)blockIdx.y * BM * K;
    const float* Bblk = B + (size_t)blockIdx.x * BN;

    float acc[TM][TN];
    #pragma unroll
    for (int i = 0; i < TM; i++)
        #pragma unroll
        for (int j = 0; j < TN; j++) acc[i][j] = 0.0f;

    // preload tile 0 into registers
    float4 ra = *(const float4*)(Ablk + (size_t)arow * K + acol);
    float4 rb = *(const float4*)(Bblk + (size_t)brow * N + bcol);

    const int nt = K / BK;
    int buf = 0;

    for (int t = 0; t < nt; t++) {
        // stage current tile regs -> smem[buf]
        As[buf][acol + 0][arow] = ra.x;
        As[buf][acol + 1][arow] = ra.y;
        As[buf][acol + 2][arow] = ra.z;
        As[buf][acol + 3][arow] = ra.w;
        *(float4*)&Bs[buf][brow][bcol] = rb;
        __syncthreads();

        // prefetch next tile gmem -> regs (overlaps with FMA block below)
        if (t + 1 < nt) {
            int k0 = (t + 1) * BK;
            ra = *(const float4*)(Ablk + (size_t)arow * K + k0 + acol);
            rb = *(const float4*)(Bblk + (size_t)(k0 + brow) * N + bcol);
        }

        #pragma unroll
        for (int kk = 0; kk < BK; kk++) {
            float va[TM], vb[TN];
            #pragma unroll
            for (int i = 0; i < TM; i++) va[i] = As[buf][kk][tr * TM + i];
            #pragma unroll
            for (int j = 0; j < TN; j++) vb[j] = Bs[buf][kk][tc * TN + j];
            #pragma unroll
            for (int i = 0; i < TM; i++)
                #pragma unroll
                for (int j = 0; j < TN; j++)
                    acc[i][j] = fmaf(va[i], vb[j], acc[i][j]);
        }
        buf ^= 1;
    }

    int row0 = blockIdx.y * BM + tr * TM;
    int col0 = blockIdx.x * BN + tc * TN;
    #pragma unroll
    for (int i = 0; i < TM; i++) {
        size_t ro = (size_t)(row0 + i) * N;
        #pragma unroll
        for (int j = 0; j < TN; j += 4) {
            int c = col0 + j;
            float4 v = make_float4(acc[i][j], acc[i][j+1], acc[i][j+2], acc[i][j+3]);
            if (BIAS) {
                const float4 bb = *(const float4*)(bias + c);
                v.x += bb.x; v.y += bb.y; v.z += bb.z; v.w += bb.w;
            }
            if (RES) {
                const float4 r = *(const float4*)(res + ro + c);
                v.x += r.x; v.y += r.y; v.z += r.z; v.w += r.w;
            }
            if (RELU) {
                v.x = fmaxf(v.x, 0.f); v.y = fmaxf(v.y, 0.f);
                v.z = fmaxf(v.z, 0.f); v.w = fmaxf(v.w, 0.f);
            }
            *(float4*)(C + ro + c) = v;
        }
    }
}

// ---------------------------------------------------------------------------
// Attention: flash-style, one thread per query row.
// grid (S/128, NH, NB), 128 threads. q,acc in registers (64 each),
// K/V tiles of 64 rows in smem, per-element online softmax (rare rescale).
// Layout of q/k/v/o: [token = n*S + s, column = h*64 + d], ld = 1024.
// ---------------------------------------------------------------------------
#define BKV 64
__global__ __launch_bounds__(128) void attn_kernel(
    const float* __restrict__ Q, const float* __restrict__ K,
    const float* __restrict__ V, float* __restrict__ O)
{
    __shared__ float Ks[BKV][HD];
    __shared__ float Vs[BKV][HD];

    int t = threadIdx.x;
    int h = blockIdx.y;
    int n = blockIdx.z;
    int qrow = blockIdx.x * 128 + t;

    const float* qp = Q + ((size_t)(n * S + qrow)) * DM + h * HD;
    float q[HD];
    #pragma unroll
    for (int i = 0; i < 16; i++) {
        float4 f = ((const float4*)qp)[i];
        q[4*i+0] = f.x; q[4*i+1] = f.y; q[4*i+2] = f.z; q[4*i+3] = f.w;
    }

    float acc[HD];
    #pragma unroll
    for (int d = 0; d < HD; d++) acc[d] = 0.0f;
    float m = -INFINITY, l = 0.0f;

    const float* kbase = K + ((size_t)n * S) * DM + h * HD;
    const float* vbase = V + ((size_t)n * S) * DM + h * HD;

    for (int kv0 = 0; kv0 < S; kv0 += BKV) {
        __syncthreads();
        #pragma unroll
        for (int i = 0; i < 8; i++) {
            int f4 = t + i * 128;
            int r = f4 >> 4, c = f4 & 15;
            *(float4*)&Ks[r][c * 4] =
                ((const float4*)(kbase + (size_t)(kv0 + r) * DM))[c];
            *(float4*)&Vs[r][c * 4] =
                ((const float4*)(vbase + (size_t)(kv0 + r) * DM))[c];
        }
        __syncthreads();

        #pragma unroll 1
        for (int j = 0; j < BKV; j++) {
            const float4* kr = (const float4*)Ks[j];
            float s = 0.0f;
            #pragma unroll
            for (int i = 0; i < 16; i++) {
                float4 f = kr[i];
                s = fmaf(q[4*i+0], f.x, s);
                s = fmaf(q[4*i+1], f.y, s);
                s = fmaf(q[4*i+2], f.z, s);
                s = fmaf(q[4*i+3], f.w, s);
            }
            s *= 0.125f;  // 1/sqrt(64)
            const float4* vr = (const float4*)Vs[j];
            if (s <= m) {
                float p = __expf(s - m);
                l += p;
                #pragma unroll
                for (int i = 0; i < 16; i++) {
                    float4 f = vr[i];
                    acc[4*i+0] = fmaf(p, f.x, acc[4*i+0]);
                    acc[4*i+1] = fmaf(p, f.y, acc[4*i+1]);
                    acc[4*i+2] = fmaf(p, f.z, acc[4*i+2]);
                    acc[4*i+3] = fmaf(p, f.w, acc[4*i+3]);
                }
            } else {
                float r = __expf(m - s);
                m = s;
                l = l * r + 1.0f;
                #pragma unroll
                for (int i = 0; i < 16; i++) {
                    float4 f = vr[i];
                    acc[4*i+0] = fmaf(acc[4*i+0], r, f.x);
                    acc[4*i+1] = fmaf(acc[4*i+1], r, f.y);
                    acc[4*i+2] = fmaf(acc[4*i+2], r, f.z);
                    acc[4*i+3] = fmaf(acc[4*i+3], r, f.w);
                }
            }
        }
    }

    float invl = 1.0f / l;
    float* op = O + ((size_t)(n * S + qrow)) * DM + h * HD;
    #pragma unroll
    for (int i = 0; i < 16; i++) {
        float4 f;
        f.x = acc[4*i+0] * invl;
        f.y = acc[4*i+1] * invl;
        f.z = acc[4*i+2] * invl;
        f.w = acc[4*i+3] * invl;
        ((float4*)op)[i] = f;
    }
}

// ---------------------------------------------------------------------------
// Launch
// ---------------------------------------------------------------------------
extern "C" void kernel_launch(void* const* d_in, const int* in_sizes, int n_in,
                              void* d_out, int out_size)
{
    const float* x    = (const float*)d_in[0];
    // d_in[1] = src_mask (unused; falsy in reference)
    const float* w_q  = (const float*)d_in[2];
    const float* w_k  = (const float*)d_in[3];
    const float* w_v  = (const float*)d_in[4];
    const float* w_0  = (const float*)d_in[5];
    const float* b_0  = (const float*)d_in[6];
    const float* w_1  = (const float*)d_in[7];
    const float* b_1  = (const float*)d_in[8];
    const float* w_2  = (const float*)d_in[9];
    const float* b_2  = (const float*)d_in[10];
    const float* g_1  = (const float*)d_in[11];
    const float* be_1 = (const float*)d_in[12];
    const float* g_2  = (const float*)d_in[13];
    const float* be_2 = (const float*)d_in[14];
    float* out = (float*)d_out;

    float *xn, *q, *k, *v, *ao, *x2, *ff;
    cudaGetSymbolAddress((void**)&xn, g_xn);
    cudaGetSymbolAddress((void**)&q,  g_q);
    cudaGetSymbolAddress((void**)&k,  g_k);
    cudaGetSymbolAddress((void**)&v,  g_v);
    cudaGetSymbolAddress((void**)&ao, g_ao);
    cudaGetSymbolAddress((void**)&x2, g_x2);
    cudaGetSymbolAddress((void**)&ff, g_ff);

    dim3 blk(256);
    dim3 gDM(DM / 128, TOK / 128);    // (8, 32)
    dim3 gFF(DFF / 128, TOK / 128);   // (32, 32)

    // LN1
    ln_kernel<<<TOK, 256>>>(x, g_1, be_1, xn);
    // QKV projections
    sgemm128<false, false, false><<<gDM, blk>>>(TOK, DM, DM, xn, w_q, nullptr, nullptr, q);
    sgemm128<false, false, false><<<gDM, blk>>>(TOK, DM, DM, xn, w_k, nullptr, nullptr, k);
    sgemm128<false, false, false><<<gDM, blk>>>(TOK, DM, DM, xn, w_v, nullptr, nullptr, v);
    // Attention
    attn_kernel<<<dim3(S / 128, NH, NB), 128>>>(q, k, v, ao);
    // Output projection + bias + residual(x) -> x2
    sgemm128<true, false, true><<<gDM, blk>>>(TOK, DM, DM, ao, w_0, b_0, x, x2);
    // LN2
    ln_kernel<<<TOK, 256>>>(x2, g_2, be_2, xn);
    // FFN
    sgemm128<true, true, false><<<gFF, blk>>>(TOK, DFF, DM, xn, w_1, b_1, nullptr, ff);
    sgemm128<true, false, true><<<gDM, blk>>>(TOK, DM, DFF, ff, w_2, b_2, x2, out);
}

// round 4
// speedup vs baseline: 3.0393x; 3.0393x over previous
#include <cuda_runtime.h>
#include <cstdint>
#include <math.h>

// ---------------------------------------------------------------------------
// Problem constants
// ---------------------------------------------------------------------------
#define NB   2
#define S    2048
#define DM   1024
#define NH   16
#define HD   64
#define DFF  4096
#define TOK  (NB * S)
#define LN_EPS 1e-5f

// ---------------------------------------------------------------------------
// Scratch (static device globals; no runtime allocation allowed)
// ---------------------------------------------------------------------------
__device__ float g_xn [(size_t)TOK * DM];
__device__ float g_q  [(size_t)TOK * DM];
__device__ float g_k  [(size_t)TOK * DM];
__device__ float g_v  [(size_t)TOK * DM];
__device__ float g_ao [(size_t)TOK * DM];
__device__ float g_x2 [(size_t)TOK * DM];
__device__ float g_ff [(size_t)TOK * DFF];
__device__ float g_wqt[(size_t)DM * DM];
__device__ float g_wkt[(size_t)DM * DM];
__device__ float g_wvt[(size_t)DM * DM];
__device__ float g_w0t[(size_t)DM * DM];
__device__ float g_w1t[(size_t)DM * DFF];
__device__ float g_w2t[(size_t)DM * DFF];
__device__ float g_vt [(size_t)NB * NH * HD * S];
__device__ float g_s  [(size_t)NB * NH * S * S];   // 512 MB scores/probs

// ---------------------------------------------------------------------------
// Helpers
// ---------------------------------------------------------------------------
__device__ __forceinline__ float to_tf32(float x) {
    uint32_t u;
    asm("cvt.rna.tf32.f32 %0, %1;" : "=r"(u) : "f"(x));
    return __uint_as_float(u);
}
__device__ __forceinline__ void mma_tf32(float* c, const uint32_t* a, const uint32_t* b) {
    asm volatile(
        "mma.sync.aligned.m16n8k8.row.col.f32.tf32.tf32.f32 "
        "{%0,%1,%2,%3}, {%4,%5,%6,%7}, {%8,%9}, {%0,%1,%2,%3};"
        : "+f"(c[0]), "+f"(c[1]), "+f"(c[2]), "+f"(c[3])
        : "r"(a[0]), "r"(a[1]), "r"(a[2]), "r"(a[3]), "r"(b[0]), "r"(b[1]));
}

// ---------------------------------------------------------------------------
// tf32 mma.sync GEMM.  C[M,N] = A[M,K] @ B^T, B stored [N][K] K-major.
// 128(M) x BN tile, BK=16, 256 threads = 8 warps (4 M x 2 N),
// warp tile 32 x (BN/2) = 2 m16-tiles x (BN/16) n8-tiles.
// Double-buffered smem [row][BK+4], register-staged prefetch.
// Batched via blockIdx.z with (inner,outer) strides; zin = inner count.
// ---------------------------------------------------------------------------
template<int BN, bool BIAS, bool RELU, bool RES>
__global__ __launch_bounds__(256) void mma_gemm(
    const float* __restrict__ A, int lda, long long sAi, long long sAo,
    const float* __restrict__ B, int ldb, long long sBi, long long sBo,
    float* __restrict__ C, int ldc, long long sCi, long long sCo,
    const float* __restrict__ bias, const float* __restrict__ res,
    int K, int zin)
{
    constexpr int BM = 128, BK = 16, SK = BK + 4;   // stride 20 -> conflict-free frags
    constexpr int WN = BN / 2;      // per-warp-column N extent (64 or 32)
    constexpr int NT = WN / 8;      // n8 tiles per warp (8 or 4)
    constexpr int BF4 = BN * 4 / 256;  // B float4 loads per thread (2 or 1)

    __shared__ float As[2][BM][SK];
    __shared__ float Bs[2][BN][SK];

    const int tid = threadIdx.x;
    const int wid = tid >> 5, lane = tid & 31;
    const int warpM = wid & 3, warpN = wid >> 2;
    const int r4 = lane >> 2, cq = lane & 3;

    const int zi = (int)(blockIdx.z % zin), zo = (int)(blockIdx.z / zin);
    const float* Ab = A + (size_t)zo * sAo + (size_t)zi * sAi + (size_t)blockIdx.y * BM * lda;
    const float* Bb = B + (size_t)zo * sBo + (size_t)zi * sBi + (size_t)blockIdx.x * BN * ldb;

    // staging map: float4 i -> row = i>>2, k-quad = i&3
    const int srow = tid >> 2, sq = tid & 3;

    float acc[2][NT][4];
    #pragma unroll
    for (int mt = 0; mt < 2; mt++)
        #pragma unroll
        for (int nt = 0; nt < NT; nt++)
            #pragma unroll
            for (int j = 0; j < 4; j++) acc[mt][nt][j] = 0.0f;

    float4 pa[2], pb[2];
    // preload tile 0
    #pragma unroll
    for (int j = 0; j < 2; j++)
        pa[j] = *(const float4*)(Ab + (size_t)(srow + j * 64) * lda + sq * 4);
    #pragma unroll
    for (int j = 0; j < BF4; j++)
        pb[j] = *(const float4*)(Bb + (size_t)(srow + j * 64) * ldb + sq * 4);

    const int nt_iters = K / BK;
    for (int t = 0; t < nt_iters; t++) {
        const int buf = t & 1;
        #pragma unroll
        for (int j = 0; j < 2; j++) {
            float4 f = pa[j];
            f.x = to_tf32(f.x); f.y = to_tf32(f.y);
            f.z = to_tf32(f.z); f.w = to_tf32(f.w);
            *(float4*)&As[buf][srow + j * 64][sq * 4] = f;
        }
        #pragma unroll
        for (int j = 0; j < BF4; j++) {
            float4 f = pb[j];
            f.x = to_tf32(f.x); f.y = to_tf32(f.y);
            f.z = to_tf32(f.z); f.w = to_tf32(f.w);
            *(float4*)&Bs[buf][srow + j * 64][sq * 4] = f;
        }
        __syncthreads();

        if (t + 1 < nt_iters) {
            const float* Ak = Ab + (t + 1) * BK;
            const float* Bk = Bb + (t + 1) * BK;
            #pragma unroll
            for (int j = 0; j < 2; j++)
                pa[j] = *(const float4*)(Ak + (size_t)(srow + j * 64) * lda + sq * 4);
            #pragma unroll
            for (int j = 0; j < BF4; j++)
                pb[j] = *(const float4*)(Bk + (size_t)(srow + j * 64) * ldb + sq * 4);
        }

        const int m0 = warpM * 32;
        const int n0 = warpN * WN;
        #pragma unroll
        for (int ks = 0; ks < 2; ks++) {
            const int k8 = ks * 8;
            uint32_t a[2][4], b[NT][2];
            #pragma unroll
            for (int mt = 0; mt < 2; mt++) {
                const int m = m0 + mt * 16 + r4;
                a[mt][0] = __float_as_uint(As[buf][m    ][k8 + cq]);
                a[mt][1] = __float_as_uint(As[buf][m + 8][k8 + cq]);
                a[mt][2] = __float_as_uint(As[buf][m    ][k8 + cq + 4]);
                a[mt][3] = __float_as_uint(As[buf][m + 8][k8 + cq + 4]);
            }
            #pragma unroll
            for (int nt = 0; nt < NT; nt++) {
                const int n = n0 + nt * 8 + r4;
                b[nt][0] = __float_as_uint(Bs[buf][n][k8 + cq]);
                b[nt][1] = __float_as_uint(Bs[buf][n][k8 + cq + 4]);
            }
            #pragma unroll
            for (int mt = 0; mt < 2; mt++)
                #pragma unroll
                for (int nt = 0; nt < NT; nt++)
                    mma_tf32(acc[mt][nt], a[mt], b[nt]);
        }
    }

    // Epilogue
    float* Cb = C + (size_t)zo * sCo + (size_t)zi * sCi;
    const float* Rb = RES ? (res + (size_t)zo * sCo + (size_t)zi * sCi) : nullptr;
    const int growb = blockIdx.y * BM + warpM * 32;
    const int gcolb = blockIdx.x * BN + warpN * WN;
    #pragma unroll
    for (int mt = 0; mt < 2; mt++) {
        #pragma unroll
        for (int half = 0; half < 2; half++) {
            const int row = growb + mt * 16 + half * 8 + r4;
            float* Crow = Cb + (size_t)row * ldc;
            const float* Rrow = RES ? (Rb + (size_t)row * ldc) : nullptr;
            #pragma unroll
            for (int nt = 0; nt < NT; nt++) {
                const int col = gcolb + nt * 8 + 2 * cq;
                float2 v;
                v.x = acc[mt][nt][half * 2 + 0];
                v.y = acc[mt][nt][half * 2 + 1];
                if (BIAS) {
                    v.x += bias[col]; v.y += bias[col + 1];
                }
                if (RES) {
                    v.x += Rrow[col]; v.y += Rrow[col + 1];
                }
                if (RELU) {
                    v.x = fmaxf(v.x, 0.f); v.y = fmaxf(v.y, 0.f);
                }
                *(float2*)(Crow + col) = v;
            }
        }
    }
}

// ---------------------------------------------------------------------------
// 32x32 tiled transpose with batched z-strides.  out[c][r] = in[r][c].
// ---------------------------------------------------------------------------
__global__ __launch_bounds__(256) void transpose32(
    const float* __restrict__ in, int ldin, long long sIi, long long sIo,
    float* __restrict__ out, int ldout, long long sOi, long long sOo, int zin)
{
    __shared__ float t[32][33];
    const int zi = (int)(blockIdx.z % zin), zo = (int)(blockIdx.z / zin);
    in  += (size_t)zo * sIo + (size_t)zi * sIi;
    out += (size_t)zo * sOo + (size_t)zi * sOi;
    const int c0 = blockIdx.x * 32, r0 = blockIdx.y * 32;
    const int tx = threadIdx.x & 31, ty = threadIdx.x >> 5;
    #pragma unroll
    for (int i = 0; i < 32; i += 8)
        t[ty + i][tx] = in[(size_t)(r0 + ty + i) * ldin + c0 + tx];
    __syncthreads();
    #pragma unroll
    for (int i = 0; i < 32; i += 8)
        out[(size_t)(c0 + ty + i) * ldout + r0 + tx] = t[tx][ty + i];
}

// ---------------------------------------------------------------------------
// Row softmax over S=2048 with 1/sqrt(HD)=0.125 scale, in place, normalized.
// ---------------------------------------------------------------------------
__global__ __launch_bounds__(256) void softmax_kernel(float* __restrict__ sm)
{
    float* p = sm + (size_t)blockIdx.x * S;
    const int t = threadIdx.x;
    float4 a = ((float4*)p)[t];
    float4 b = ((float4*)p)[t + 256];
    const float sc = 0.125f;
    a.x *= sc; a.y *= sc; a.z *= sc; a.w *= sc;
    b.x *= sc; b.y *= sc; b.z *= sc; b.w *= sc;

    float m = fmaxf(fmaxf(fmaxf(a.x, a.y), fmaxf(a.z, a.w)),
                    fmaxf(fmaxf(b.x, b.y), fmaxf(b.z, b.w)));
    __shared__ float red[256];
    red[t] = m; __syncthreads();
    #pragma unroll
    for (int st = 128; st > 0; st >>= 1) {
        if (t < st) red[t] = fmaxf(red[t], red[t + st]);
        __syncthreads();
    }
    m = red[0]; __syncthreads();

    a.x = __expf(a.x - m); a.y = __expf(a.y - m);
    a.z = __expf(a.z - m); a.w = __expf(a.w - m);
    b.x = __expf(b.x - m); b.y = __expf(b.y - m);
    b.z = __expf(b.z - m); b.w = __expf(b.w - m);
    float s8 = a.x + a.y + a.z + a.w + b.x + b.y + b.z + b.w;
    red[t] = s8; __syncthreads();
    #pragma unroll
    for (int st = 128; st > 0; st >>= 1) {
        if (t < st) red[t] += red[t + st];
        __syncthreads();
    }
    const float inv = 1.0f / red[0];
    a.x *= inv; a.y *= inv; a.z *= inv; a.w *= inv;
    b.x *= inv; b.y *= inv; b.z *= inv; b.w *= inv;
    ((float4*)p)[t] = a;
    ((float4*)p)[t + 256] = b;
}

// ---------------------------------------------------------------------------
// LayerNorm: one block per row (1024 floats), 256 threads, float4
// ---------------------------------------------------------------------------
__global__ __launch_bounds__(256) void ln_kernel(
    const float* __restrict__ x, const float* __restrict__ g,
    const float* __restrict__ b, float* __restrict__ y)
{
    int row = blockIdx.x;
    int t = threadIdx.x;
    float4 v = ((const float4*)(x + (size_t)row * DM))[t];
    float sum = v.x + v.y + v.z + v.w;
    float sq  = v.x*v.x + v.y*v.y + v.z*v.z + v.w*v.w;
    __shared__ float s1[256], s2[256];
    s1[t] = sum; s2[t] = sq;
    __syncthreads();
    #pragma unroll
    for (int st = 128; st > 0; st >>= 1) {
        if (t < st) { s1[t] += s1[t + st]; s2[t] += s2[t + st]; }
        __syncthreads();
    }
    float mu  = s1[0] * (1.0f / DM);
    float var = s2[0] * (1.0f / DM) - mu * mu;
    float inv = rsqrtf(var + LN_EPS);
    float4 gv = ((const float4*)g)[t];
    float4 bv = ((const float4*)b)[t];
    float4 o;
    o.x = (v.x - mu) * inv * gv.x + bv.x;
    o.y = (v.y - mu) * inv * gv.y + bv.y;
    o.z = (v.z - mu) * inv * gv.z + bv.z;
    o.w = (v.w - mu) * inv * gv.w + bv.w;
    ((float4*)(y + (size_t)row * DM))[t] = o;
}

// ---------------------------------------------------------------------------
// Launch
// ---------------------------------------------------------------------------
extern "C" void kernel_launch(void* const* d_in, const int* in_sizes, int n_in,
                              void* d_out, int out_size)
{
    const float* x    = (const float*)d_in[0];
    const float* w_q  = (const float*)d_in[2];
    const float* w_k  = (const float*)d_in[3];
    const float* w_v  = (const float*)d_in[4];
    const float* w_0  = (const float*)d_in[5];
    const float* b_0  = (const float*)d_in[6];
    const float* w_1  = (const float*)d_in[7];
    const float* b_1  = (const float*)d_in[8];
    const float* w_2  = (const float*)d_in[9];
    const float* b_2  = (const float*)d_in[10];
    const float* g_1  = (const float*)d_in[11];
    const float* be_1 = (const float*)d_in[12];
    const float* g_2  = (const float*)d_in[13];
    const float* be_2 = (const float*)d_in[14];
    float* out = (float*)d_out;

    float *xn, *q, *k, *v, *ao, *x2, *ff, *wqt, *wkt, *wvt, *w0t, *w1t, *w2t, *vt, *sg;
    cudaGetSymbolAddress((void**)&xn, g_xn);
    cudaGetSymbolAddress((void**)&q,  g_q);
    cudaGetSymbolAddress((void**)&k,  g_k);
    cudaGetSymbolAddress((void**)&v,  g_v);
    cudaGetSymbolAddress((void**)&ao, g_ao);
    cudaGetSymbolAddress((void**)&x2, g_x2);
    cudaGetSymbolAddress((void**)&ff, g_ff);
    cudaGetSymbolAddress((void**)&wqt, g_wqt);
    cudaGetSymbolAddress((void**)&wkt, g_wkt);
    cudaGetSymbolAddress((void**)&wvt, g_wvt);
    cudaGetSymbolAddress((void**)&w0t, g_w0t);
    cudaGetSymbolAddress((void**)&w1t, g_w1t);
    cudaGetSymbolAddress((void**)&w2t, g_w2t);
    cudaGetSymbolAddress((void**)&vt, g_vt);
    cudaGetSymbolAddress((void**)&sg, g_s);

    // Weight transposes: W[K][N] -> Wt[N][K]
    transpose32<<<dim3(DM/32,  DM/32,  1), 256>>>(w_q, DM, 0, 0, wqt, DM,  0, 0, 1);
    transpose32<<<dim3(DM/32,  DM/32,  1), 256>>>(w_k, DM, 0, 0, wkt, DM,  0, 0, 1);
    transpose32<<<dim3(DM/32,  DM/32,  1), 256>>>(w_v, DM, 0, 0, wvt, DM,  0, 0, 1);
    transpose32<<<dim3(DM/32,  DM/32,  1), 256>>>(w_0, DM, 0, 0, w0t, DM,  0, 0, 1);
    transpose32<<<dim3(DFF/32, DM/32,  1), 256>>>(w_1, DFF, 0, 0, w1t, DM, 0, 0, 1);
    transpose32<<<dim3(DM/32,  DFF/32, 1), 256>>>(w_2, DM, 0, 0, w2t, DFF, 0, 0, 1);

    // LN1
    ln_kernel<<<TOK, 256>>>(x, g_1, be_1, xn);

    // QKV projections
    mma_gemm<128,false,false,false><<<dim3(8, 32, 1), 256>>>(
        xn, DM, 0, 0, wqt, DM, 0, 0, q, DM, 0, 0, nullptr, nullptr, DM, 1);
    mma_gemm<128,false,false,false><<<dim3(8, 32, 1), 256>>>(
        xn, DM, 0, 0, wkt, DM, 0, 0, k, DM, 0, 0, nullptr, nullptr, DM, 1);
    mma_gemm<128,false,false,false><<<dim3(8, 32, 1), 256>>>(
        xn, DM, 0, 0, wvt, DM, 0, 0, v, DM, 0, 0, nullptr, nullptr, DM, 1);

    // V^T per (n,h): [kv][d] -> [d][kv]
    transpose32<<<dim3(HD/32, S/32, NB*NH), 256>>>(
        v, DM, HD, (long long)S*DM, vt, S, (long long)HD*S, 16LL*HD*S, NH);

    // scores[z][q][kv] = Q . K
    mma_gemm<128,false,false,false><<<dim3(S/128, S/128, NB*NH), 256>>>(
        q, DM, HD, (long long)S*DM,
        k, DM, HD, (long long)S*DM,
        sg, S, (long long)S*S, 16LL*S*S,
        nullptr, nullptr, HD, NH);

    // softmax rows (scale + normalize, in place)
    softmax_kernel<<<NB*NH*S, 256>>>(sg);

    // attn_out = P @ V   (B operand = V^T [d][kv] K-major)
    mma_gemm<64,false,false,false><<<dim3(1, S/128, NB*NH), 256>>>(
        sg, S, (long long)S*S, 16LL*S*S,
        vt, S, (long long)HD*S, 16LL*HD*S,
        ao, DM, HD, (long long)S*DM,
        nullptr, nullptr, S, NH);

    // x2 = x + ao @ W0 + b0
    mma_gemm<128,true,false,true><<<dim3(8, 32, 1), 256>>>(
        ao, DM, 0, 0, w0t, DM, 0, 0, x2, DM, 0, 0, b_0, x, DM, 1);

    // LN2
    ln_kernel<<<TOK, 256>>>(x2, g_2, be_2, xn);

    // ff = relu(xn @ W1 + b1)
    mma_gemm<128,true,true,false><<<dim3(DFF/128, 32, 1), 256>>>(
        xn, DM, 0, 0, w1t, DM, 0, 0, ff, DFF, 0, 0, b_1, nullptr, DM, 1);

    // out = x2 + ff @ W2 + b2
    mma_gemm<128,true,false,true><<<dim3(8, 32, 1), 256>>>(
        ff, DFF, 0, 0, w2t, DFF, 0, 0, out, DM, 0, 0, b_2, x2, DFF, 1);
}